// round 9
// baseline (speedup 1.0000x reference)
#include <cuda_runtime.h>
#include <cuda_fp16.h>
#include <cstdint>

#define DIM 128
#define MSZ (DIM * DIM)

// fp32 tables for direct copies: g_U[e] = map for pos e+1, e in [0,254]
__device__ __align__(16) float g_U[255 * MSZ];
// fp16 images, chunked SW128 layout:
//  g_A16[s] : level-8 entry (pos 256+s), [m][k], HI ONLY (32KB = 16384 halfs)
//  g_B16[e] : U[e], [n][k], hi+lo (64KB): [hi c0 16K][hi c1 16K][lo c0][lo c1]
//  g_AW[b]  : W_b^T = U[1+b], [m][k], hi+lo
__device__ __align__(1024) __half g_A16[256 * 16384];
__device__ __align__(1024) __half g_B16[255 * 32768];
__device__ __align__(1024) __half g_AW[2 * 32768];
// expm scratch
__device__ __align__(16) float g_Bm[2 * MSZ];
__device__ __align__(16) float g_B2[2 * MSZ];
__device__ __align__(16) float g_B3[2 * MSZ];
__device__ __align__(16) float g_B4[2 * MSZ];
__device__ __align__(16) float g_X0[2 * MSZ];
__device__ __align__(16) float g_X1[2 * MSZ];
// global barrier state (monotonic across graph replays)
__device__ unsigned g_count = 0;   // k_expm
__device__ unsigned g_count2 = 0;  // k_levels
__device__ unsigned g_epoch = 0;

#define SW128(o) ((o) ^ (((o) >> 3) & 0x70))

// ------------------------------------------------------------- PTX helpers
__device__ __forceinline__ uint32_t smem_to_u32(const void* p) {
    uint32_t a;
    asm("{ .reg .u64 t; cvta.to.shared.u64 t, %1; cvt.u32.u64 %0, t; }" : "=r"(a) : "l"(p));
    return a;
}
#define MBARRIER_INIT(addr, cnt) \
    asm volatile("mbarrier.init.shared.b64 [%0], %1;" :: "r"((uint32_t)(addr)), "r"((uint32_t)(cnt)) : "memory")
#define MBARRIER_EXPECT_TX(addr, tx) \
    asm volatile("mbarrier.arrive.expect_tx.shared.b64 _, [%0], %1;" :: "r"((uint32_t)(addr)), "r"((uint32_t)(tx)) : "memory")
#define MBARRIER_ARRIVE(addr) \
    asm volatile("mbarrier.arrive.shared.b64 _, [%0];" :: "r"((uint32_t)(addr)) : "memory")
#define MBARRIER_WAIT_PARITY(mbar_smem_addr, phase_parity) do { \
    uint32_t _mbar = (uint32_t)(mbar_smem_addr); \
    uint32_t _parity = (uint32_t)(phase_parity); \
    uint32_t _done; \
    asm volatile("{\n\t.reg .pred p;\n\t" \
        "mbarrier.try_wait.parity.acquire.cta.shared::cta.b64 p, [%1], %2;\n\t" \
        "selp.b32 %0, 1, 0, p;\n\t}" : "=r"(_done) : "r"(_mbar), "r"(_parity) : "memory"); \
    if (!_done) { \
        asm volatile("{\n\t.reg .pred P1;\n\t" \
            "WAIT_LOOP_%=:\n\t" \
            "mbarrier.try_wait.parity.acquire.cta.shared::cta.b64 P1, [%0], %1, 0x989680;\n\t" \
            "@P1 bra.uni WAIT_DONE_%=;\n\t" \
            "bra.uni WAIT_LOOP_%=;\n\t" \
            "WAIT_DONE_%=:\n\t}" :: "r"(_mbar), "r"(_parity) : "memory"); \
    } \
} while (0)
__device__ __forceinline__ void bulk_ld(uint32_t dst, const void* src, uint32_t bytes, uint32_t mbar) {
    asm volatile("cp.async.bulk.shared::cta.global.mbarrier::complete_tx::bytes [%0], [%1], %2, [%3];"
                 :: "r"(dst), "l"(src), "r"(bytes), "r"(mbar) : "memory");
}
#define LDSM4(r0, r1, r2, r3, a) \
    asm volatile("ldmatrix.sync.aligned.m8n8.x4.shared.b16 {%0,%1,%2,%3}, [%4];" \
                 : "=r"(r0), "=r"(r1), "=r"(r2), "=r"(r3) : "r"(a))
#define MMA16816(c0, c1, c2, c3, a0, a1, a2, a3, b0, b1) \
    asm volatile("mma.sync.aligned.m16n8k16.row.col.f32.f16.f16.f32 " \
                 "{%0,%1,%2,%3}, {%4,%5,%6,%7}, {%8,%9}, {%0,%1,%2,%3};" \
                 : "+f"(c0), "+f"(c1), "+f"(c2), "+f"(c3) \
                 : "r"(a0), "r"(a1), "r"(a2), "r"(a3), "r"(b0), "r"(b1))

// hi/lo fp16 split write into a SW128 image
__device__ __forceinline__ void img_put(__half* img, int row, int k, float v) {
    int idx = ((k >> 6) << 13) + (SW128(row * 128 + (k & 63) * 2) >> 1);
    __half h = __float2half_rn(v);
    img[idx] = h;
    img[idx + 16384] = __float2half_rn(v - __half2float(h));
}

// ------------------------------------------------- global spin barriers
__device__ __forceinline__ void gbar_on(unsigned* ctr, unsigned target) {
    asm volatile("fence.proxy.async;" ::: "memory");
    __syncthreads();
    if (threadIdx.x == 0) {
        __threadfence();
        atomicAdd(ctr, 1u);
        unsigned v;
        do {
            asm volatile("ld.acquire.gpu.u32 %0, [%1];" : "=r"(v) : "l"(ctr) : "memory");
            if ((int)(v - target) >= 0) break;
            __nanosleep(64);
        } while (true);
    }
    __syncthreads();
}

// ------------------------------------- fp32 64x64 tile engine (.cg loads)
__device__ __forceinline__ void mm64cg(const float* __restrict__ A, const float* __restrict__ B,
                                       int rowBase, int colBase, float acc[4][4]) {
    __shared__ __align__(16) float As[16][64];
    __shared__ __align__(16) float Bs[16][64];
    int t = threadIdx.x;
    int tx = t & 15, ty = t >> 4;
#pragma unroll
    for (int i = 0; i < 4; i++)
#pragma unroll
        for (int j = 0; j < 4; j++) acc[i][j] = 0.0f;
    for (int kc = 0; kc < DIM; kc += 16) {
        {
            int ar = t >> 2, acg = (t & 3) * 4;
            float4 av = __ldcg((const float4*)&A[(rowBase + ar) * DIM + kc + acg]);
            As[acg + 0][ar] = av.x; As[acg + 1][ar] = av.y;
            As[acg + 2][ar] = av.z; As[acg + 3][ar] = av.w;
        }
        {
            int br = t >> 4, bcg = (t & 15) * 4;
            *(float4*)&Bs[br][bcg] = __ldcg((const float4*)&B[(kc + br) * DIM + colBase + bcg]);
        }
        __syncthreads();
#pragma unroll
        for (int kk = 0; kk < 16; kk++) {
            float a[4], bb[4];
            *(float4*)a  = *(const float4*)&As[kk][ty * 4];
            *(float4*)bb = *(const float4*)&Bs[kk][tx * 4];
#pragma unroll
            for (int i = 0; i < 4; i++)
#pragma unroll
                for (int j = 0; j < 4; j++) acc[i][j] += a[i] * bb[j];
        }
        __syncthreads();
    }
}
__device__ __forceinline__ void store64(float* __restrict__ C, int rowBase, int colBase,
                                        float acc[4][4]) {
    int tx = threadIdx.x & 15, ty = threadIdx.x >> 4;
#pragma unroll
    for (int i = 0; i < 4; i++)
#pragma unroll
        for (int j = 0; j < 4; j++)
            C[(rowBase + ty * 4 + i) * DIM + colBase + tx * 4 + j] = acc[i][j];
}

__global__ void k_epoch() { atomicAdd(&g_epoch, 1u); }

// -------------------------------------------------------------------------
// k_expm: 8 CTAs (2 matrices x 4 quads). prep -> B2 -> B3,B4 -> PS init ->
//         3 Horner -> 6 squarings -> write U[0..2] + AW + B16[0..2].
// 13 cheap barriers over 8 CTAs.
// -------------------------------------------------------------------------
#define NBARE 13u
__global__ void __launch_bounds__(256) k_expm(const float* __restrict__ P) {
    const int cta = blockIdx.x;     // 0..7
    const int t = threadIdx.x;
    __shared__ unsigned sE;
    if (t == 0) sE = *(volatile unsigned*)&g_epoch;
    __syncthreads();
    const unsigned base = (sE - 1u) * NBARE * 8u;
    int barId = 0;
#define GBAR() gbar_on(&g_count, base + (unsigned)(++barId) * 8u)

    const float c0 = 1.0f, c1 = 1.0f, c2 = 0.5f, c3 = 1.0f / 6.0f, c4 = 1.0f / 24.0f;
    const float c5 = 1.0f / 120.0f, c6 = 1.0f / 720.0f, c7 = 1.0f / 5040.0f;
    const float c8 = 1.0f / 40320.0f, c9 = 2.75573192e-6f, c10 = 2.75573192e-7f;
    const float c11 = 2.50521084e-8f, c12 = 2.08767570e-9f, c13 = 1.60590438e-10f;
    const float c14 = 1.14707456e-11f, c15 = 7.64716373e-13f, c16 = 4.77947733e-14f;

    const int b = cta >> 2, quad = cta & 3;
    const int rB = (quad >> 1) * 64, cB = (quad & 1) * 64;

    // prep: Bm = (P - P^T)/64
    for (int idx = cta * 256 + t; idx < 2 * MSZ; idx += 2048) {
        int bb = idx >> 14, r = (idx >> 7) & 127, c = idx & 127;
        float h = __ldg(&P[bb * MSZ + r * DIM + c]) - __ldg(&P[bb * MSZ + c * DIM + r]);
        g_Bm[idx] = h * (1.0f / 64.0f);
    }
    GBAR();
    {   // B2
        float acc[4][4];
        mm64cg(g_Bm + b * MSZ, g_Bm + b * MSZ, rB, cB, acc);
        store64(g_B2 + b * MSZ, rB, cB, acc);
    }
    GBAR();
    {   // B3 then B4 (2 matmuls per CTA)
        float acc[4][4];
        mm64cg(g_B2 + b * MSZ, g_Bm + b * MSZ, rB, cB, acc);
        store64(g_B3 + b * MSZ, rB, cB, acc);
        float acc2[4][4];
        mm64cg(g_B2 + b * MSZ, g_B2 + b * MSZ, rB, cB, acc2);
        store64(g_B4 + b * MSZ, rB, cB, acc2);
    }
    GBAR();
    // PS init: X0 = c12 I + c13 B + c14 B2 + c15 B3 + c16 B4
    for (int idx = cta * 256 + t; idx < 2 * MSZ; idx += 2048) {
        int r = (idx >> 7) & 127, c = idx & 127;
        float v = c13 * __ldcg(&g_Bm[idx]) + c14 * __ldcg(&g_B2[idx]) +
                  c15 * __ldcg(&g_B3[idx]) + c16 * __ldcg(&g_B4[idx]);
        if (r == c) v += c12;
        g_X0[idx] = v;
    }
    GBAR();
    {
        float qs[3][4] = {{c8, c9, c10, c11}, {c4, c5, c6, c7}, {c0, c1, c2, c3}};
        int sel = 0;
        for (int h = 0; h < 3; h++) {
            const float* T = (sel ? g_X1 : g_X0) + b * MSZ;
            float* Y       = (sel ? g_X0 : g_X1) + b * MSZ;
            float acc[4][4];
            mm64cg(T, g_B4 + b * MSZ, rB, cB, acc);
            int tx = t & 15, ty = t >> 4;
#pragma unroll
            for (int i = 0; i < 4; i++) {
                int gr = rB + ty * 4 + i;
#pragma unroll
                for (int j = 0; j < 4; j++) {
                    int gc = cB + tx * 4 + j;
                    int e = b * MSZ + gr * DIM + gc;
                    float v = acc[i][j] + qs[h][1] * __ldcg(&g_Bm[e]) +
                              qs[h][2] * __ldcg(&g_B2[e]) + qs[h][3] * __ldcg(&g_B3[e]);
                    if (gr == gc) v += qs[h][0];
                    Y[gr * DIM + gc] = v;
                }
            }
            sel ^= 1;
            GBAR();
        }
        for (int sq = 0; sq < 6; sq++) {
            const float* X = (sel ? g_X1 : g_X0) + b * MSZ;
            float* Y       = (sel ? g_X0 : g_X1) + b * MSZ;
            float acc[4][4];
            mm64cg(X, X, rB, cB, acc);
            store64(Y, rB, cB, acc);
            sel ^= 1;
            GBAR();
        }
        // after 9 flips: result E in X1
    }
    // tail: U[0]=I, U[1+b]=E_b^T, AW images, B16[0..2] images
    for (int i = cta * 256 + t; i < MSZ; i += 2048) {
        int r = i >> 7, c = i & 127;
        float v = (r == c) ? 1.0f : 0.0f;
        g_U[i] = v;
        img_put(g_B16, r, c, v);
    }
    for (int bm = 0; bm < 2; bm++) {
        const float* E = g_X1 + bm * MSZ;
        for (int i = cta * 256 + t; i < MSZ; i += 2048) {
            int r = i >> 7, c = i & 127;           // E[r][c]
            float v = __ldcg(&E[i]);
            g_U[(size_t)(1 + bm) * MSZ + c * DIM + r] = v;   // U = E^T
            img_put(g_AW + (size_t)bm * 32768, c, r, v);     // A[m=c][k=r] = E[k][m]
            img_put(g_B16 + (size_t)(1 + bm) * 32768, r, c, v); // B[n=r][k=c] = E[n][k]
        }
    }
#undef GBAR
}

// ===========================================================================
// HMMA engines.
// prod64: warp tile 32x64 (wr 0..3, wc 0..1) — used by k_levels (table build)
// ===========================================================================
__device__ __forceinline__ void prod64(uint32_t aimg, uint32_t bimg,
                                       int wr, int wc, int lane, float acc[2][8][4]) {
    int rA0 = (wr * 32 + (lane & 15)) * 128;
    int seg = (lane >> 4) * 16;
    int rB = (lane & 15) * 128;
#pragma unroll
    for (int ks = 0; ks < 8; ks++) {
        uint32_t coff = (uint32_t)(ks >> 2) * 16384u;
        int kw2 = (ks & 3) * 32;
        uint32_t a0, a1, a2, a3, a4, a5, a6, a7;
        LDSM4(a0, a1, a2, a3, aimg + coff + (uint32_t)SW128(rA0 + kw2 + seg));
        LDSM4(a4, a5, a6, a7, aimg + coff + (uint32_t)SW128(rA0 + 2048 + kw2 + seg));
#pragma unroll
        for (int ng = 0; ng < 4; ng++) {
            uint32_t b0, b1, b2, b3;
            LDSM4(b0, b1, b2, b3,
                  bimg + coff + (uint32_t)SW128((wc * 4 + ng) * 2048 + rB + kw2 + seg));
            MMA16816(acc[0][2 * ng][0], acc[0][2 * ng][1], acc[0][2 * ng][2], acc[0][2 * ng][3],
                     a0, a1, a2, a3, b0, b2);
            MMA16816(acc[0][2 * ng + 1][0], acc[0][2 * ng + 1][1], acc[0][2 * ng + 1][2], acc[0][2 * ng + 1][3],
                     a0, a1, a2, a3, b1, b3);
            MMA16816(acc[1][2 * ng][0], acc[1][2 * ng][1], acc[1][2 * ng][2], acc[1][2 * ng][3],
                     a4, a5, a6, a7, b0, b2);
            MMA16816(acc[1][2 * ng + 1][0], acc[1][2 * ng + 1][1], acc[1][2 * ng + 1][2], acc[1][2 * ng + 1][3],
                     a4, a5, a6, a7, b1, b3);
        }
    }
}
__device__ __forceinline__ void store_frag64(float* __restrict__ C, int wr, int wc, int lane,
                                             float acc[2][8][4]) {
#pragma unroll
    for (int rt = 0; rt < 2; rt++) {
        int row0 = wr * 32 + rt * 16 + (lane >> 2);
#pragma unroll
        for (int ct = 0; ct < 8; ct++) {
            int col = wc * 64 + ct * 8 + (lane & 3) * 2;
            *(float2*)&C[row0 * DIM + col]       = make_float2(acc[rt][ct][0], acc[rt][ct][1]);
            *(float2*)&C[(row0 + 8) * DIM + col] = make_float2(acc[rt][ct][2], acc[rt][ct][3]);
        }
    }
}

// ---------------------------------------------------------------------------
// prodT: warp tile 64x32 (wr 0..1 row bands, wc 0..3 col bands) — k_final.
// All 8 LDSM per ks issued up front; 16 hi-MMAs then 16 lo-MMAs.
// ---------------------------------------------------------------------------
__device__ __forceinline__ void prodT(uint32_t aimg, uint32_t bhi, uint32_t blo,
                                      int wr, int wc, int lane, float acc[4][4][4]) {
    int rA = (wr * 64 + (lane & 15)) * 128;
    int seg = (lane >> 4) * 16;
    int rB = (wc * 32 + (lane & 15)) * 128;
#pragma unroll
    for (int ks = 0; ks < 8; ks++) {
        uint32_t coff = (uint32_t)(ks >> 2) * 16384u;
        int kw2 = (ks & 3) * 32;
        uint32_t a[4][4];
#pragma unroll
        for (int at = 0; at < 4; at++)
            LDSM4(a[at][0], a[at][1], a[at][2], a[at][3],
                  aimg + coff + (uint32_t)SW128(rA + at * 2048 + kw2 + seg));
        uint32_t h0[4], h1[4], l0[4], l1[4];
        LDSM4(h0[0], h0[1], h0[2], h0[3], bhi + coff + (uint32_t)SW128(rB + kw2 + seg));
        LDSM4(h1[0], h1[1], h1[2], h1[3], bhi + coff + (uint32_t)SW128(rB + 2048 + kw2 + seg));
        LDSM4(l0[0], l0[1], l0[2], l0[3], blo + coff + (uint32_t)SW128(rB + kw2 + seg));
        LDSM4(l1[0], l1[1], l1[2], l1[3], blo + coff + (uint32_t)SW128(rB + 2048 + kw2 + seg));
#pragma unroll
        for (int at = 0; at < 4; at++) {
            MMA16816(acc[at][0][0], acc[at][0][1], acc[at][0][2], acc[at][0][3],
                     a[at][0], a[at][1], a[at][2], a[at][3], h0[0], h0[2]);
            MMA16816(acc[at][1][0], acc[at][1][1], acc[at][1][2], acc[at][1][3],
                     a[at][0], a[at][1], a[at][2], a[at][3], h0[1], h0[3]);
            MMA16816(acc[at][2][0], acc[at][2][1], acc[at][2][2], acc[at][2][3],
                     a[at][0], a[at][1], a[at][2], a[at][3], h1[0], h1[2]);
            MMA16816(acc[at][3][0], acc[at][3][1], acc[at][3][2], acc[at][3][3],
                     a[at][0], a[at][1], a[at][2], a[at][3], h1[1], h1[3]);
        }
#pragma unroll
        for (int at = 0; at < 4; at++) {
            MMA16816(acc[at][0][0], acc[at][0][1], acc[at][0][2], acc[at][0][3],
                     a[at][0], a[at][1], a[at][2], a[at][3], l0[0], l0[2]);
            MMA16816(acc[at][1][0], acc[at][1][1], acc[at][1][2], acc[at][1][3],
                     a[at][0], a[at][1], a[at][2], a[at][3], l0[1], l0[3]);
            MMA16816(acc[at][2][0], acc[at][2][1], acc[at][2][2], acc[at][2][3],
                     a[at][0], a[at][1], a[at][2], a[at][3], l1[0], l1[2]);
            MMA16816(acc[at][3][0], acc[at][3][1], acc[at][3][2], acc[at][3][3],
                     a[at][0], a[at][1], a[at][2], a[at][3], l1[1], l1[3]);
        }
    }
}
__device__ __forceinline__ void store_fragT(float* __restrict__ C, int wr, int wc, int lane,
                                            float acc[4][4][4]) {
#pragma unroll
    for (int at = 0; at < 4; at++) {
        int row0 = wr * 64 + at * 16 + (lane >> 2);
#pragma unroll
        for (int ct = 0; ct < 4; ct++) {
            int col = wc * 32 + ct * 8 + (lane & 3) * 2;
            __stcs((float2*)&C[row0 * DIM + col],       make_float2(acc[at][ct][0], acc[at][ct][1]));
            __stcs((float2*)&C[(row0 + 8) * DIM + col], make_float2(acc[at][ct][2], acc[at][ct][3]));
        }
    }
}

// ===========================================================================
// k_levels: levels 2..8 in ONE launch. 128 persistent CTAs, 6 spin barriers.
// level j entry s: C = W_{s&1} @ U[offPrev + s>>1]  (3-product hi/lo)
// j<8: write fp32 g_U[e] + B-img g_B16[e]; j=8: write A-img g_A16[s] (hi only)
// ===========================================================================
#define NBARL 6u
#define UL_SMEM (1024 + 131072)
__global__ void __launch_bounds__(256, 1) k_levels() {
    extern __shared__ char smem[];
    uint32_t sb = smem_to_u32(smem);
    const int cta = blockIdx.x;     // 0..127
    const int t = threadIdx.x, wid = t >> 5, lane = t & 31, wr = wid >> 1, wc = wid & 1;
    __shared__ unsigned sE;
    if (t == 0) sE = *(volatile unsigned*)&g_epoch;
    __syncthreads();
    const unsigned base = (sE - 1u) * NBARL * 128u;
    int barId = 0;
    if (t == 0) { MBARRIER_INIT(sb + 0, 1); MBARRIER_INIT(sb + 8, 1); }
    __syncthreads();
    uint32_t AH = sb + 1024, BH = AH + 32768, AL = BH + 32768, BL = AL + 32768;
    int ph = 0;

    for (int lvl = 2; lvl <= 8; lvl++) {
        int ntask = 1 << lvl;
        int offPrev = (1 << (lvl - 1)) - 1, offCur = (1 << lvl) - 1;
        for (int s = cta; s < ntask; s += 128) {
            __syncthreads();
            int e = offCur + s;
            const char* As = (const char*)(g_AW + (size_t)(s & 1) * 32768);
            const char* Bs = (const char*)(g_B16 + (size_t)(offPrev + (s >> 1)) * 32768);
            if (t == 0) {
                MBARRIER_EXPECT_TX(sb + 0, 65536);
                bulk_ld(AH, As, 32768, sb + 0);
                bulk_ld(BH, Bs, 32768, sb + 0);
                MBARRIER_EXPECT_TX(sb + 8, 65536);
                bulk_ld(AL, As + 32768, 32768, sb + 8);
                bulk_ld(BL, Bs + 32768, 32768, sb + 8);
            }
            float acc[2][8][4];
#pragma unroll
            for (int i = 0; i < 2; i++)
#pragma unroll
                for (int j = 0; j < 8; j++)
#pragma unroll
                    for (int kq = 0; kq < 4; kq++) acc[i][j][kq] = 0.0f;

            MBARRIER_WAIT_PARITY(sb + 0, ph);
            prod64(AH, BH, wr, wc, lane, acc);
            MBARRIER_WAIT_PARITY(sb + 8, ph);
            prod64(AH, BL, wr, wc, lane, acc);
            prod64(AL, BH, wr, wc, lane, acc);
            ph ^= 1;
            __syncthreads();
            float* Cs = (float*)(smem + 1024);
            store_frag64(Cs, wr, wc, lane, acc);
            __syncthreads();
            if (lvl < 8) {
                float* Ug = g_U + (size_t)e * MSZ;
                for (int i = t * 4; i < MSZ; i += 1024)
                    *(float4*)&Ug[i] = *(const float4*)&Cs[i];
                __half* dst = g_B16 + (size_t)e * 32768;
                for (int item = t; item < 2048; item += 256) {
                    int n = item & 127, kb = item >> 7;
                    __half hv[8], lv[8];
#pragma unroll
                    for (int kk = 0; kk < 8; kk++) {
                        float v = Cs[(kb * 8 + kk) * DIM + n];
                        __half h = __float2half_rn(v);
                        hv[kk] = h;
                        lv[kk] = __float2half_rn(v - __half2float(h));
                    }
                    int k0 = kb * 8;
                    int idx = ((k0 >> 6) << 13) + (SW128(n * 128 + (k0 & 63) * 2) >> 1);
                    *(uint4*)&dst[idx] = *(uint4*)hv;
                    *(uint4*)&dst[idx + 16384] = *(uint4*)lv;
                }
            } else {
                __half* dst = g_A16 + (size_t)s * 16384;
                for (int item = t; item < 2048; item += 256) {
                    int kb = item & 15, m = item >> 4;
                    __half hv[8];
#pragma unroll
                    for (int kk = 0; kk < 8; kk++)
                        hv[kk] = __float2half_rn(Cs[m * DIM + kb * 8 + kk]);
                    int k0 = kb * 8;
                    int idx = ((k0 >> 6) << 13) + (SW128(m * 128 + (k0 & 63) * 2) >> 1);
                    *(uint4*)&dst[idx] = *(uint4*)hv;
                }
            }
        }
        if (lvl < 8) gbar_on(&g_count2, base + (unsigned)(++barId) * 128u);
    }
}

// ===========================================================================
// k_final: persistent, 152 CTAs, 8 compute warps (64x32 tiles) + 1 producer.
// 2-slot ring, 96KB/slot: [A 32K][Bhi 32K][Blo 32K].
// ===========================================================================
#define SLOT_SZ 98304
#define FINAL_SMEM (1024 + 2 * SLOT_SZ)

__global__ void __launch_bounds__(288, 1) k_final(const int* __restrict__ uniq,
                                                  float* __restrict__ out, int n) {
    extern __shared__ char smem[];
    uint32_t sb = smem_to_u32(smem);
    int t = threadIdx.x;
    if (t == 0) {
#pragma unroll
        for (int s = 0; s < 2; s++) {
            MBARRIER_INIT(sb + s * 16, 1);        // full
            MBARRIER_INIT(sb + s * 16 + 8, 256);  // empty
        }
    }
    __syncthreads();

    if (t >= 256) {                 // producer warp
        if (t == 256) {
            unsigned u = 0;
            for (int i = blockIdx.x; i < n; i += gridDim.x) {
                int pos = __ldg(&uniq[i]);
                if (pos < 256) continue;
                int r = pos & 255, qi = (pos >> 8) - 1;
                unsigned s = u & 1, rd = u >> 1;
                if (u >= 2) MBARRIER_WAIT_PARITY(sb + s * 16 + 8, (rd - 1) & 1);
                MBARRIER_EXPECT_TX(sb + s * 16, 98304);
                uint32_t dst = sb + 1024 + s * SLOT_SZ;
                bulk_ld(dst,         g_A16 + (size_t)r * 16384,          32768, sb + s * 16);
                bulk_ld(dst + 32768, g_B16 + (size_t)qi * 32768,         32768, sb + s * 16);
                bulk_ld(dst + 65536, g_B16 + (size_t)qi * 32768 + 16384, 32768, sb + s * 16);
                u++;
            }
        }
        return;
    }

    int wid = t >> 5, lane = t & 31, wr = wid & 1, wc = wid >> 1;
    unsigned u = 0;
    for (int i = blockIdx.x; i < n; i += gridDim.x) {
        int pos = uniq[i];
        float* C = out + (size_t)i * MSZ;
        if (pos < 256) {
            const float* src = g_U + (size_t)(pos - 1) * MSZ;
            for (int e = t * 4; e < MSZ; e += 1024) {
                float4 v = *(const float4*)&src[e];
                __stcs((float4*)&C[e], v);
            }
            continue;
        }
        unsigned s = u & 1, rd = u >> 1;
        u++;
        uint32_t basep = sb + 1024 + s * SLOT_SZ;

        float acc[4][4][4];
#pragma unroll
        for (int a = 0; a < 4; a++)
#pragma unroll
            for (int bq = 0; bq < 4; bq++)
#pragma unroll
                for (int c = 0; c < 4; c++) acc[a][bq][c] = 0.0f;

        MBARRIER_WAIT_PARITY(sb + s * 16, rd & 1);
        prodT(basep, basep + 32768, basep + 65536, wr, wc, lane, acc);
        MBARRIER_ARRIVE(sb + s * 16 + 8);
        store_fragT(C, wr, wc, lane, acc);
    }
}

// ===========================================================================
extern "C" void kernel_launch(void* const* d_in, const int* in_sizes, int n_in,
                              void* d_out, int out_size) {
    const int* uniq = (const int*)d_in[0];
    const float* P  = (const float*)d_in[1];
    float* out = (float*)d_out;
    int n = in_sizes[0];

    k_epoch<<<1, 1>>>();
    k_expm<<<8, 256>>>(P);

    cudaFuncSetAttribute(k_levels, cudaFuncAttributeMaxDynamicSharedMemorySize, UL_SMEM);
    k_levels<<<128, 256, UL_SMEM>>>();

    cudaFuncSetAttribute(k_final, cudaFuncAttributeMaxDynamicSharedMemorySize, FINAL_SMEM);
    k_final<<<152, 288, FINAL_SMEM>>>(uniq, out, n);
}

// round 10
// speedup vs baseline: 1.1512x; 1.1512x over previous
#include <cuda_runtime.h>
#include <cuda_fp16.h>
#include <cstdint>

#define DIM 128
#define MSZ (DIM * DIM)

// fp32 tables for direct copies: g_U[e] = map for pos e+1, e in [0,254]
__device__ __align__(16) float g_U[255 * MSZ];
// fp16 images, chunked SW128 layout:
//  g_A16[s] : level-8 entry (pos 256+s), [m][k], HI ONLY (32KB = 16384 halfs)
//  g_B16[e] : U[e], [n][k], hi+lo (64KB): [hi c0 16K][hi c1 16K][lo c0][lo c1]
//             (lo kept for accurate 3-product table builds; k_final reads hi only)
//  g_AW[b]  : W_b^T = U[1+b], [m][k], hi+lo
__device__ __align__(1024) __half g_A16[256 * 16384];
__device__ __align__(1024) __half g_B16[255 * 32768];
__device__ __align__(1024) __half g_AW[2 * 32768];
// expm scratch
__device__ __align__(16) float g_Bm[2 * MSZ];
__device__ __align__(16) float g_B2[2 * MSZ];
__device__ __align__(16) float g_B3[2 * MSZ];
__device__ __align__(16) float g_B4[2 * MSZ];
__device__ __align__(16) float g_X0[2 * MSZ];
__device__ __align__(16) float g_X1[2 * MSZ];
// global barrier state (monotonic across graph replays)
__device__ unsigned g_count = 0;   // k_expm
__device__ unsigned g_count2 = 0;  // k_levels
__device__ unsigned g_epoch = 0;

#define SW128(o) ((o) ^ (((o) >> 3) & 0x70))

// ------------------------------------------------------------- PTX helpers
__device__ __forceinline__ uint32_t smem_to_u32(const void* p) {
    uint32_t a;
    asm("{ .reg .u64 t; cvta.to.shared.u64 t, %1; cvt.u32.u64 %0, t; }" : "=r"(a) : "l"(p));
    return a;
}
#define MBARRIER_INIT(addr, cnt) \
    asm volatile("mbarrier.init.shared.b64 [%0], %1;" :: "r"((uint32_t)(addr)), "r"((uint32_t)(cnt)) : "memory")
#define MBARRIER_EXPECT_TX(addr, tx) \
    asm volatile("mbarrier.arrive.expect_tx.shared.b64 _, [%0], %1;" :: "r"((uint32_t)(addr)), "r"((uint32_t)(tx)) : "memory")
#define MBARRIER_ARRIVE(addr) \
    asm volatile("mbarrier.arrive.shared.b64 _, [%0];" :: "r"((uint32_t)(addr)) : "memory")
#define MBARRIER_WAIT_PARITY(mbar_smem_addr, phase_parity) do { \
    uint32_t _mbar = (uint32_t)(mbar_smem_addr); \
    uint32_t _parity = (uint32_t)(phase_parity); \
    uint32_t _done; \
    asm volatile("{\n\t.reg .pred p;\n\t" \
        "mbarrier.try_wait.parity.acquire.cta.shared::cta.b64 p, [%1], %2;\n\t" \
        "selp.b32 %0, 1, 0, p;\n\t}" : "=r"(_done) : "r"(_mbar), "r"(_parity) : "memory"); \
    if (!_done) { \
        asm volatile("{\n\t.reg .pred P1;\n\t" \
            "WAIT_LOOP_%=:\n\t" \
            "mbarrier.try_wait.parity.acquire.cta.shared::cta.b64 P1, [%0], %1, 0x989680;\n\t" \
            "@P1 bra.uni WAIT_DONE_%=;\n\t" \
            "bra.uni WAIT_LOOP_%=;\n\t" \
            "WAIT_DONE_%=:\n\t}" :: "r"(_mbar), "r"(_parity) : "memory"); \
    } \
} while (0)
__device__ __forceinline__ void bulk_ld(uint32_t dst, const void* src, uint32_t bytes, uint32_t mbar) {
    asm volatile("cp.async.bulk.shared::cta.global.mbarrier::complete_tx::bytes [%0], [%1], %2, [%3];"
                 :: "r"(dst), "l"(src), "r"(bytes), "r"(mbar) : "memory");
}
#define LDSM4(r0, r1, r2, r3, a) \
    asm volatile("ldmatrix.sync.aligned.m8n8.x4.shared.b16 {%0,%1,%2,%3}, [%4];" \
                 : "=r"(r0), "=r"(r1), "=r"(r2), "=r"(r3) : "r"(a))
#define MMA16816(c0, c1, c2, c3, a0, a1, a2, a3, b0, b1) \
    asm volatile("mma.sync.aligned.m16n8k16.row.col.f32.f16.f16.f32 " \
                 "{%0,%1,%2,%3}, {%4,%5,%6,%7}, {%8,%9}, {%0,%1,%2,%3};" \
                 : "+f"(c0), "+f"(c1), "+f"(c2), "+f"(c3) \
                 : "r"(a0), "r"(a1), "r"(a2), "r"(a3), "r"(b0), "r"(b1))

// hi/lo fp16 split write into a SW128 image
__device__ __forceinline__ void img_put(__half* img, int row, int k, float v) {
    int idx = ((k >> 6) << 13) + (SW128(row * 128 + (k & 63) * 2) >> 1);
    __half h = __float2half_rn(v);
    img[idx] = h;
    img[idx + 16384] = __float2half_rn(v - __half2float(h));
}

// ------------------------------------------------- global spin barriers
__device__ __forceinline__ void gbar_on(unsigned* ctr, unsigned target) {
    asm volatile("fence.proxy.async;" ::: "memory");
    __syncthreads();
    if (threadIdx.x == 0) {
        __threadfence();
        atomicAdd(ctr, 1u);
        unsigned v;
        do {
            asm volatile("ld.acquire.gpu.u32 %0, [%1];" : "=r"(v) : "l"(ctr) : "memory");
            if ((int)(v - target) >= 0) break;
            __nanosleep(64);
        } while (true);
    }
    __syncthreads();
}

// ------------------------------------- fp32 64x64 tile engine (.cg loads)
__device__ __forceinline__ void mm64cg(const float* __restrict__ A, const float* __restrict__ B,
                                       int rowBase, int colBase, float acc[4][4]) {
    __shared__ __align__(16) float As[16][64];
    __shared__ __align__(16) float Bs[16][64];
    int t = threadIdx.x;
    int tx = t & 15, ty = t >> 4;
#pragma unroll
    for (int i = 0; i < 4; i++)
#pragma unroll
        for (int j = 0; j < 4; j++) acc[i][j] = 0.0f;
    for (int kc = 0; kc < DIM; kc += 16) {
        {
            int ar = t >> 2, acg = (t & 3) * 4;
            float4 av = __ldcg((const float4*)&A[(rowBase + ar) * DIM + kc + acg]);
            As[acg + 0][ar] = av.x; As[acg + 1][ar] = av.y;
            As[acg + 2][ar] = av.z; As[acg + 3][ar] = av.w;
        }
        {
            int br = t >> 4, bcg = (t & 15) * 4;
            *(float4*)&Bs[br][bcg] = __ldcg((const float4*)&B[(kc + br) * DIM + colBase + bcg]);
        }
        __syncthreads();
#pragma unroll
        for (int kk = 0; kk < 16; kk++) {
            float a[4], bb[4];
            *(float4*)a  = *(const float4*)&As[kk][ty * 4];
            *(float4*)bb = *(const float4*)&Bs[kk][tx * 4];
#pragma unroll
            for (int i = 0; i < 4; i++)
#pragma unroll
                for (int j = 0; j < 4; j++) acc[i][j] += a[i] * bb[j];
        }
        __syncthreads();
    }
}
__device__ __forceinline__ void store64(float* __restrict__ C, int rowBase, int colBase,
                                        float acc[4][4]) {
    int tx = threadIdx.x & 15, ty = threadIdx.x >> 4;
#pragma unroll
    for (int i = 0; i < 4; i++)
#pragma unroll
        for (int j = 0; j < 4; j++)
            C[(rowBase + ty * 4 + i) * DIM + colBase + tx * 4 + j] = acc[i][j];
}

__global__ void k_epoch() { atomicAdd(&g_epoch, 1u); }

// -------------------------------------------------------------------------
// k_expm: 8 CTAs (2 matrices x 4 quads). prep -> B2 -> B3,B4 -> PS init ->
//         3 Horner -> 6 squarings -> write U[0..2] + AW + B16[0..2].
// -------------------------------------------------------------------------
#define NBARE 13u
__global__ void __launch_bounds__(256) k_expm(const float* __restrict__ P) {
    const int cta = blockIdx.x;     // 0..7
    const int t = threadIdx.x;
    __shared__ unsigned sE;
    if (t == 0) sE = *(volatile unsigned*)&g_epoch;
    __syncthreads();
    const unsigned base = (sE - 1u) * NBARE * 8u;
    int barId = 0;
#define GBAR() gbar_on(&g_count, base + (unsigned)(++barId) * 8u)

    const float c0 = 1.0f, c1 = 1.0f, c2 = 0.5f, c3 = 1.0f / 6.0f, c4 = 1.0f / 24.0f;
    const float c5 = 1.0f / 120.0f, c6 = 1.0f / 720.0f, c7 = 1.0f / 5040.0f;
    const float c8 = 1.0f / 40320.0f, c9 = 2.75573192e-6f, c10 = 2.75573192e-7f;
    const float c11 = 2.50521084e-8f, c12 = 2.08767570e-9f, c13 = 1.60590438e-10f;
    const float c14 = 1.14707456e-11f, c15 = 7.64716373e-13f, c16 = 4.77947733e-14f;

    const int b = cta >> 2, quad = cta & 3;
    const int rB = (quad >> 1) * 64, cB = (quad & 1) * 64;

    for (int idx = cta * 256 + t; idx < 2 * MSZ; idx += 2048) {
        int bb = idx >> 14, r = (idx >> 7) & 127, c = idx & 127;
        float h = __ldg(&P[bb * MSZ + r * DIM + c]) - __ldg(&P[bb * MSZ + c * DIM + r]);
        g_Bm[idx] = h * (1.0f / 64.0f);
    }
    GBAR();
    {   // B2
        float acc[4][4];
        mm64cg(g_Bm + b * MSZ, g_Bm + b * MSZ, rB, cB, acc);
        store64(g_B2 + b * MSZ, rB, cB, acc);
    }
    GBAR();
    {   // B3, B4
        float acc[4][4];
        mm64cg(g_B2 + b * MSZ, g_Bm + b * MSZ, rB, cB, acc);
        store64(g_B3 + b * MSZ, rB, cB, acc);
        float acc2[4][4];
        mm64cg(g_B2 + b * MSZ, g_B2 + b * MSZ, rB, cB, acc2);
        store64(g_B4 + b * MSZ, rB, cB, acc2);
    }
    GBAR();
    for (int idx = cta * 256 + t; idx < 2 * MSZ; idx += 2048) {
        int r = (idx >> 7) & 127, c = idx & 127;
        float v = c13 * __ldcg(&g_Bm[idx]) + c14 * __ldcg(&g_B2[idx]) +
                  c15 * __ldcg(&g_B3[idx]) + c16 * __ldcg(&g_B4[idx]);
        if (r == c) v += c12;
        g_X0[idx] = v;
    }
    GBAR();
    {
        float qs[3][4] = {{c8, c9, c10, c11}, {c4, c5, c6, c7}, {c0, c1, c2, c3}};
        int sel = 0;
        for (int h = 0; h < 3; h++) {
            const float* T = (sel ? g_X1 : g_X0) + b * MSZ;
            float* Y       = (sel ? g_X0 : g_X1) + b * MSZ;
            float acc[4][4];
            mm64cg(T, g_B4 + b * MSZ, rB, cB, acc);
            int tx = t & 15, ty = t >> 4;
#pragma unroll
            for (int i = 0; i < 4; i++) {
                int gr = rB + ty * 4 + i;
#pragma unroll
                for (int j = 0; j < 4; j++) {
                    int gc = cB + tx * 4 + j;
                    int e = b * MSZ + gr * DIM + gc;
                    float v = acc[i][j] + qs[h][1] * __ldcg(&g_Bm[e]) +
                              qs[h][2] * __ldcg(&g_B2[e]) + qs[h][3] * __ldcg(&g_B3[e]);
                    if (gr == gc) v += qs[h][0];
                    Y[gr * DIM + gc] = v;
                }
            }
            sel ^= 1;
            GBAR();
        }
        for (int sq = 0; sq < 6; sq++) {
            const float* X = (sel ? g_X1 : g_X0) + b * MSZ;
            float* Y       = (sel ? g_X0 : g_X1) + b * MSZ;
            float acc[4][4];
            mm64cg(X, X, rB, cB, acc);
            store64(Y, rB, cB, acc);
            sel ^= 1;
            GBAR();
        }
    }
    // tail: U[0]=I, U[1+b]=E^T, AW + B16[0..2] images (E in X1)
    for (int i = cta * 256 + t; i < MSZ; i += 2048) {
        int r = i >> 7, c = i & 127;
        float v = (r == c) ? 1.0f : 0.0f;
        g_U[i] = v;
        img_put(g_B16, r, c, v);
    }
    for (int bm = 0; bm < 2; bm++) {
        const float* E = g_X1 + bm * MSZ;
        for (int i = cta * 256 + t; i < MSZ; i += 2048) {
            int r = i >> 7, c = i & 127;
            float v = __ldcg(&E[i]);
            g_U[(size_t)(1 + bm) * MSZ + c * DIM + r] = v;
            img_put(g_AW + (size_t)bm * 32768, c, r, v);
            img_put(g_B16 + (size_t)(1 + bm) * 32768, r, c, v);
        }
    }
#undef GBAR
}

// ===========================================================================
// prod64: warp tile 32x64 (wr 0..3, wc 0..1) — k_levels table build (3-product)
// ===========================================================================
__device__ __forceinline__ void prod64(uint32_t aimg, uint32_t bimg,
                                       int wr, int wc, int lane, float acc[2][8][4]) {
    int rA0 = (wr * 32 + (lane & 15)) * 128;
    int seg = (lane >> 4) * 16;
    int rB = (lane & 15) * 128;
#pragma unroll
    for (int ks = 0; ks < 8; ks++) {
        uint32_t coff = (uint32_t)(ks >> 2) * 16384u;
        int kw2 = (ks & 3) * 32;
        uint32_t a0, a1, a2, a3, a4, a5, a6, a7;
        LDSM4(a0, a1, a2, a3, aimg + coff + (uint32_t)SW128(rA0 + kw2 + seg));
        LDSM4(a4, a5, a6, a7, aimg + coff + (uint32_t)SW128(rA0 + 2048 + kw2 + seg));
#pragma unroll
        for (int ng = 0; ng < 4; ng++) {
            uint32_t b0, b1, b2, b3;
            LDSM4(b0, b1, b2, b3,
                  bimg + coff + (uint32_t)SW128((wc * 4 + ng) * 2048 + rB + kw2 + seg));
            MMA16816(acc[0][2 * ng][0], acc[0][2 * ng][1], acc[0][2 * ng][2], acc[0][2 * ng][3],
                     a0, a1, a2, a3, b0, b2);
            MMA16816(acc[0][2 * ng + 1][0], acc[0][2 * ng + 1][1], acc[0][2 * ng + 1][2], acc[0][2 * ng + 1][3],
                     a0, a1, a2, a3, b1, b3);
            MMA16816(acc[1][2 * ng][0], acc[1][2 * ng][1], acc[1][2 * ng][2], acc[1][2 * ng][3],
                     a4, a5, a6, a7, b0, b2);
            MMA16816(acc[1][2 * ng + 1][0], acc[1][2 * ng + 1][1], acc[1][2 * ng + 1][2], acc[1][2 * ng + 1][3],
                     a4, a5, a6, a7, b1, b3);
        }
    }
}
__device__ __forceinline__ void store_frag64(float* __restrict__ C, int wr, int wc, int lane,
                                             float acc[2][8][4]) {
#pragma unroll
    for (int rt = 0; rt < 2; rt++) {
        int row0 = wr * 32 + rt * 16 + (lane >> 2);
#pragma unroll
        for (int ct = 0; ct < 8; ct++) {
            int col = wc * 64 + ct * 8 + (lane & 3) * 2;
            *(float2*)&C[row0 * DIM + col]       = make_float2(acc[rt][ct][0], acc[rt][ct][1]);
            *(float2*)&C[(row0 + 8) * DIM + col] = make_float2(acc[rt][ct][2], acc[rt][ct][3]);
        }
    }
}

// ---------------------------------------------------------------------------
// prodS: warp tile 32x32 single product (wr 0..3, wc 0..3) — k_final.
// Per ks: 2 A-LDSM + 2 B-LDSM, 8 MMAs.
// ---------------------------------------------------------------------------
__device__ __forceinline__ void prodS(uint32_t aimg, uint32_t bimg,
                                      int wr, int wc, int lane, float acc[2][4][4]) {
    int rA = (wr * 32 + (lane & 15)) * 128;
    int seg = (lane >> 4) * 16;
    int rB = (wc * 32 + (lane & 15)) * 128;
#pragma unroll
    for (int ks = 0; ks < 8; ks++) {
        uint32_t coff = (uint32_t)(ks >> 2) * 16384u;
        int kw2 = (ks & 3) * 32;
        uint32_t a0[4], a1[4], b0[4], b1[4];
        LDSM4(a0[0], a0[1], a0[2], a0[3], aimg + coff + (uint32_t)SW128(rA + kw2 + seg));
        LDSM4(a1[0], a1[1], a1[2], a1[3], aimg + coff + (uint32_t)SW128(rA + 2048 + kw2 + seg));
        LDSM4(b0[0], b0[1], b0[2], b0[3], bimg + coff + (uint32_t)SW128(rB + kw2 + seg));
        LDSM4(b1[0], b1[1], b1[2], b1[3], bimg + coff + (uint32_t)SW128(rB + 2048 + kw2 + seg));
        MMA16816(acc[0][0][0], acc[0][0][1], acc[0][0][2], acc[0][0][3],
                 a0[0], a0[1], a0[2], a0[3], b0[0], b0[2]);
        MMA16816(acc[0][1][0], acc[0][1][1], acc[0][1][2], acc[0][1][3],
                 a0[0], a0[1], a0[2], a0[3], b0[1], b0[3]);
        MMA16816(acc[0][2][0], acc[0][2][1], acc[0][2][2], acc[0][2][3],
                 a0[0], a0[1], a0[2], a0[3], b1[0], b1[2]);
        MMA16816(acc[0][3][0], acc[0][3][1], acc[0][3][2], acc[0][3][3],
                 a0[0], a0[1], a0[2], a0[3], b1[1], b1[3]);
        MMA16816(acc[1][0][0], acc[1][0][1], acc[1][0][2], acc[1][0][3],
                 a1[0], a1[1], a1[2], a1[3], b0[0], b0[2]);
        MMA16816(acc[1][1][0], acc[1][1][1], acc[1][1][2], acc[1][1][3],
                 a1[0], a1[1], a1[2], a1[3], b0[1], b0[3]);
        MMA16816(acc[1][2][0], acc[1][2][1], acc[1][2][2], acc[1][2][3],
                 a1[0], a1[1], a1[2], a1[3], b1[0], b1[2]);
        MMA16816(acc[1][3][0], acc[1][3][1], acc[1][3][2], acc[1][3][3],
                 a1[0], a1[1], a1[2], a1[3], b1[1], b1[3]);
    }
}
__device__ __forceinline__ void store_fragS(float* __restrict__ C, int wr, int wc, int lane,
                                            float acc[2][4][4]) {
#pragma unroll
    for (int at = 0; at < 2; at++) {
        int row0 = wr * 32 + at * 16 + (lane >> 2);
#pragma unroll
        for (int ct = 0; ct < 4; ct++) {
            int col = wc * 32 + ct * 8 + (lane & 3) * 2;
            *(float2*)&C[row0 * DIM + col]       = make_float2(acc[at][ct][0], acc[at][ct][1]);
            *(float2*)&C[(row0 + 8) * DIM + col] = make_float2(acc[at][ct][2], acc[at][ct][3]);
        }
    }
}

// ===========================================================================
// k_levels: levels 2..8 in ONE launch. 128 persistent CTAs, 6 spin barriers.
// ===========================================================================
#define NBARL 6u
#define UL_SMEM (1024 + 131072)
__global__ void __launch_bounds__(256, 1) k_levels() {
    extern __shared__ char smem[];
    uint32_t sb = smem_to_u32(smem);
    const int cta = blockIdx.x;     // 0..127
    const int t = threadIdx.x, wid = t >> 5, lane = t & 31, wr = wid >> 1, wc = wid & 1;
    __shared__ unsigned sE;
    if (t == 0) sE = *(volatile unsigned*)&g_epoch;
    __syncthreads();
    const unsigned base = (sE - 1u) * NBARL * 128u;
    int barId = 0;
    if (t == 0) { MBARRIER_INIT(sb + 0, 1); MBARRIER_INIT(sb + 8, 1); }
    __syncthreads();
    uint32_t AH = sb + 1024, BH = AH + 32768, AL = BH + 32768, BL = AL + 32768;
    int ph = 0;

    for (int lvl = 2; lvl <= 8; lvl++) {
        int ntask = 1 << lvl;
        int offPrev = (1 << (lvl - 1)) - 1, offCur = (1 << lvl) - 1;
        for (int s = cta; s < ntask; s += 128) {
            __syncthreads();
            int e = offCur + s;
            const char* As = (const char*)(g_AW + (size_t)(s & 1) * 32768);
            const char* Bs = (const char*)(g_B16 + (size_t)(offPrev + (s >> 1)) * 32768);
            if (t == 0) {
                MBARRIER_EXPECT_TX(sb + 0, 65536);
                bulk_ld(AH, As, 32768, sb + 0);
                bulk_ld(BH, Bs, 32768, sb + 0);
                MBARRIER_EXPECT_TX(sb + 8, 65536);
                bulk_ld(AL, As + 32768, 32768, sb + 8);
                bulk_ld(BL, Bs + 32768, 32768, sb + 8);
            }
            float acc[2][8][4];
#pragma unroll
            for (int i = 0; i < 2; i++)
#pragma unroll
                for (int j = 0; j < 8; j++)
#pragma unroll
                    for (int kq = 0; kq < 4; kq++) acc[i][j][kq] = 0.0f;

            MBARRIER_WAIT_PARITY(sb + 0, ph);
            prod64(AH, BH, wr, wc, lane, acc);
            MBARRIER_WAIT_PARITY(sb + 8, ph);
            prod64(AH, BL, wr, wc, lane, acc);
            prod64(AL, BH, wr, wc, lane, acc);
            ph ^= 1;
            __syncthreads();
            float* Cs = (float*)(smem + 1024);
            store_frag64(Cs, wr, wc, lane, acc);
            __syncthreads();
            if (lvl < 8) {
                float* Ug = g_U + (size_t)e * MSZ;
                for (int i = t * 4; i < MSZ; i += 1024)
                    *(float4*)&Ug[i] = *(const float4*)&Cs[i];
                __half* dst = g_B16 + (size_t)e * 32768;
                for (int item = t; item < 2048; item += 256) {
                    int n = item & 127, kb = item >> 7;
                    __half hv[8], lv[8];
#pragma unroll
                    for (int kk = 0; kk < 8; kk++) {
                        float v = Cs[(kb * 8 + kk) * DIM + n];
                        __half h = __float2half_rn(v);
                        hv[kk] = h;
                        lv[kk] = __float2half_rn(v - __half2float(h));
                    }
                    int k0 = kb * 8;
                    int idx = ((k0 >> 6) << 13) + (SW128(n * 128 + (k0 & 63) * 2) >> 1);
                    *(uint4*)&dst[idx] = *(uint4*)hv;
                    *(uint4*)&dst[idx + 16384] = *(uint4*)lv;
                }
            } else {
                __half* dst = g_A16 + (size_t)s * 16384;
                for (int item = t; item < 2048; item += 256) {
                    int kb = item & 15, m = item >> 4;
                    __half hv[8];
#pragma unroll
                    for (int kk = 0; kk < 8; kk++)
                        hv[kk] = __float2half_rn(Cs[m * DIM + kb * 8 + kk]);
                    int k0 = kb * 8;
                    int idx = ((k0 >> 6) << 13) + (SW128(m * 128 + (k0 & 63) * 2) >> 1);
                    *(uint4*)&dst[idx] = *(uint4*)hv;
                }
            }
        }
        if (lvl < 8) gbar_on(&g_count2, base + (unsigned)(++barId) * 128u);
    }
}

// ===========================================================================
// k_final: persistent, 152 CTAs, 16 compute warps (32x32 tiles) + 1 producer.
// Single fp16 product (A hi x B hi). 3-slot ring, 64KB/slot: [A 32K][B 32K].
// ===========================================================================
#define SLOT_SZ 65536
#define FINAL_SMEM (1024 + 3 * SLOT_SZ)

__global__ void __launch_bounds__(544, 1) k_final(const int* __restrict__ uniq,
                                                  float* __restrict__ out, int n) {
    extern __shared__ char smem[];
    uint32_t sb = smem_to_u32(smem);
    int t = threadIdx.x;
    if (t == 0) {
#pragma unroll
        for (int s = 0; s < 3; s++) {
            MBARRIER_INIT(sb + s * 16, 1);        // full
            MBARRIER_INIT(sb + s * 16 + 8, 512);  // empty (16 compute warps)
        }
    }
    __syncthreads();

    if (t >= 512) {                 // producer warp
        if (t == 512) {
            unsigned u = 0;
            for (int i = blockIdx.x; i < n; i += gridDim.x) {
                int pos = __ldg(&uniq[i]);
                if (pos < 256) continue;
                int r = pos & 255, qi = (pos >> 8) - 1;
                unsigned s = u % 3, rd = u / 3;
                if (u >= 3) MBARRIER_WAIT_PARITY(sb + s * 16 + 8, (rd - 1) & 1);
                MBARRIER_EXPECT_TX(sb + s * 16, 65536);
                uint32_t dst = sb + 1024 + s * SLOT_SZ;
                bulk_ld(dst,         g_A16 + (size_t)r * 16384,  32768, sb + s * 16);
                bulk_ld(dst + 32768, g_B16 + (size_t)qi * 32768, 32768, sb + s * 16);
                u++;
            }
        }
        return;
    }

    int wid = t >> 5, lane = t & 31, wr = wid >> 2, wc = wid & 3;
    unsigned u = 0;
    for (int i = blockIdx.x; i < n; i += gridDim.x) {
        int pos = uniq[i];
        float* C = out + (size_t)i * MSZ;
        if (pos < 256) {
            const float* src = g_U + (size_t)(pos - 1) * MSZ;
            for (int e = t * 4; e < MSZ; e += 2048)
                *(float4*)&C[e] = *(const float4*)&src[e];
            continue;
        }
        unsigned s = u % 3, rd = u / 3;
        u++;
        uint32_t basep = sb + 1024 + s * SLOT_SZ;

        float acc[2][4][4];
#pragma unroll
        for (int a = 0; a < 2; a++)
#pragma unroll
            for (int bq = 0; bq < 4; bq++)
#pragma unroll
                for (int c = 0; c < 4; c++) acc[a][bq][c] = 0.0f;

        MBARRIER_WAIT_PARITY(sb + s * 16, rd & 1);
        prodS(basep, basep + 32768, wr, wc, lane, acc);
        MBARRIER_ARRIVE(sb + s * 16 + 8);
        store_fragS(C, wr, wc, lane, acc);
    }
}

// ===========================================================================
extern "C" void kernel_launch(void* const* d_in, const int* in_sizes, int n_in,
                              void* d_out, int out_size) {
    const int* uniq = (const int*)d_in[0];
    const float* P  = (const float*)d_in[1];
    float* out = (float*)d_out;
    int n = in_sizes[0];

    k_epoch<<<1, 1>>>();
    k_expm<<<8, 256>>>(P);

    cudaFuncSetAttribute(k_levels, cudaFuncAttributeMaxDynamicSharedMemorySize, UL_SMEM);
    k_levels<<<128, 256, UL_SMEM>>>();

    cudaFuncSetAttribute(k_final, cudaFuncAttributeMaxDynamicSharedMemorySize, FINAL_SMEM);
    k_final<<<152, 544, FINAL_SMEM>>>(uniq, out, n);
}